// round 2
// baseline (speedup 1.0000x reference)
#include <cuda_runtime.h>
#include <math.h>

#define NN 100000
#define NE 3200000
#define MAXD 256

// ---------------- static device scratch (allocation-free contract) ----------------
__device__ float g_bufA[(size_t)NN * MAXD];
__device__ float g_bufB[(size_t)NN * MAXD];
__device__ float g_bufC[(size_t)NN * MAXD];
__device__ int   g_src[NE];
__device__ int   g_dst[NE];
__device__ int   g_cnt[NN];
__device__ int   g_rowptr[NN + 1];
__device__ int   g_woff[NN];
__device__ int   g_csr_src[NE];
__device__ float g_csr_w[NE];
__device__ float g_di[NN];
__device__ float g_dis[NN];
__device__ float g_bn[512];      // [0,256) colsum, [256,512) colsumsq
__device__ float g_scale[256];
__device__ float g_shift[256];
__device__ int   g_is64;

// ---------------- small utility kernels ----------------
__global__ void k_zero_i(int* p, int n) {
    for (int i = blockIdx.x * blockDim.x + threadIdx.x; i < n; i += gridDim.x * blockDim.x)
        p[i] = 0;
}
__global__ void k_zero_f(float* p, int n) {
    for (int i = blockIdx.x * blockDim.x + threadIdx.x; i < n; i += gridDim.x * blockDim.x)
        p[i] = 0.f;
}

// Detect whether edge_index buffer is int64 or int32.
// Int64 values in [0, N) have all-zero high words -> every odd 32-bit word is 0.
__global__ void k_detect(const unsigned int* __restrict__ w, int* __restrict__ flag) {
    __shared__ unsigned int anyNZ;
    if (threadIdx.x == 0) anyNZ = 0u;
    __syncthreads();
    unsigned int v = w[2 * threadIdx.x + 1];   // odd words within first 512 words
    if (v) atomicOr(&anyNZ, 1u);
    __syncthreads();
    if (threadIdx.x == 0) *flag = (anyNZ == 0u) ? 1 : 0;
}

// convert edge list (int32 or int64 per flag) -> int32, count in-degree of dst
__global__ void k_prep_edges(const void* __restrict__ ei_raw, const int* __restrict__ flag,
                             int* __restrict__ src, int* __restrict__ dst,
                             int* __restrict__ cnt, int E, int n) {
    const int is64 = *flag;
    const long long* ei64 = (const long long*)ei_raw;
    const int* ei32 = (const int*)ei_raw;
    for (int e = blockIdx.x * blockDim.x + threadIdx.x; e < E; e += gridDim.x * blockDim.x) {
        int s, d;
        if (is64) {
            s = (int)ei64[e];
            d = (int)ei64[(size_t)E + e];
        } else {
            s = ei32[e];
            d = ei32[(size_t)E + e];
        }
        // bounds guard: never crash on a mis-parse
        if ((unsigned)s >= (unsigned)n) s = 0;
        if ((unsigned)d >= (unsigned)n) d = 0;
        src[e] = s;
        dst[e] = d;
        atomicAdd(&cnt[d], 1);
    }
}

__global__ void k_deg(const int* __restrict__ cnt, float* __restrict__ di,
                      float* __restrict__ dis, int n) {
    int i = blockIdx.x * blockDim.x + threadIdx.x;
    if (i < n) {
        float dg = (float)cnt[i] + 1.0f;
        di[i]  = 1.0f / dg;
        dis[i] = rsqrtf(dg);
    }
}

// single-block exclusive scan of cnt -> rowptr (and woff copy)
__global__ void k_scan(const int* __restrict__ cnt, int* __restrict__ rowptr,
                       int* __restrict__ woff, int n) {
    __shared__ int partial[1024];
    int t = threadIdx.x;
    int chunk = (n + 1023) / 1024;
    int beg = t * chunk;
    int end = beg + chunk; if (end > n) end = n;
    if (beg > n) beg = n;
    int s = 0;
    for (int i = beg; i < end; i++) s += cnt[i];
    partial[t] = s;
    __syncthreads();
    for (int off = 1; off < 1024; off <<= 1) {
        int v = (t >= off) ? partial[t - off] : 0;
        __syncthreads();
        partial[t] += v;
        __syncthreads();
    }
    int run = (t == 0) ? 0 : partial[t - 1];
    for (int i = beg; i < end; i++) {
        rowptr[i] = run;
        woff[i]   = run;
        run += cnt[i];
    }
    if (t == 1023) rowptr[n] = partial[1023];
}

// scatter edges into CSR-by-dst, precompute edge weight dis[src]*dis[dst]
__global__ void k_csr(const int* __restrict__ src, const int* __restrict__ dst,
                      const float* __restrict__ dis, int* __restrict__ woff,
                      int* __restrict__ csrs, float* __restrict__ csrw, int E) {
    for (int e = blockIdx.x * blockDim.x + threadIdx.x; e < E; e += gridDim.x * blockDim.x) {
        int d = dst[e];
        int pos = atomicAdd(&woff[d], 1);
        int s = src[e];
        if (pos < E) {
            csrs[pos] = s;
            csrw[pos] = dis[s] * dis[d];
        }
    }
}

// ---------------- aggregation: warp-per-node gather ----------------
// out[i,:] = sum_{e in row(i)} w_e * in[src_e,:] + di[i]*in[i,:]  (+bias, +BN partials if EPI)
template <int D, bool EPI>
__global__ __launch_bounds__(256) void k_agg(
    const float* __restrict__ xin, float* __restrict__ xout,
    const int* __restrict__ rowptr, const int* __restrict__ csrs,
    const float* __restrict__ csrw, const float* __restrict__ di, int n,
    const float* __restrict__ bias, float* __restrict__ bnsum, float* __restrict__ bnsq)
{
    constexpr int CPL = D / 32;
    int lane = threadIdx.x & 31;
    int node = blockIdx.x * 8 + (threadIdx.x >> 5);
    float acc[CPL];
#pragma unroll
    for (int j = 0; j < CPL; j++) acc[j] = 0.f;

    if (node < n) {
        int beg = rowptr[node], end = rowptr[node + 1];
        for (int e = beg; e < end; e++) {
            int s = csrs[e];
            float w = csrw[e];
            const float* r = xin + (size_t)s * D + lane;
#pragma unroll
            for (int j = 0; j < CPL; j++) acc[j] += w * __ldg(r + 32 * j);
        }
        float dii = di[node];
        const float* r = xin + (size_t)node * D + lane;
#pragma unroll
        for (int j = 0; j < CPL; j++) {
            acc[j] += dii * __ldg(r + 32 * j);
            if (EPI) acc[j] += bias[lane + 32 * j];
            xout[(size_t)node * D + lane + 32 * j] = acc[j];
        }
    }
    if constexpr (EPI) {
        __shared__ float csum[D];
        __shared__ float csq[D];
        for (int t = threadIdx.x; t < D; t += blockDim.x) { csum[t] = 0.f; csq[t] = 0.f; }
        __syncthreads();
        if (node < n) {
#pragma unroll
            for (int j = 0; j < CPL; j++) {
                atomicAdd(&csum[lane + 32 * j], acc[j]);
                atomicAdd(&csq[lane + 32 * j], acc[j] * acc[j]);
            }
        }
        __syncthreads();
        for (int t = threadIdx.x; t < D; t += blockDim.x) {
            atomicAdd(&bnsum[t], csum[t]);
            atomicAdd(&bnsq[t], csq[t]);
        }
    }
}

// ---------------- register-tiled fp32 GEMM: C[M,Nc] = A[M,K] @ W[K,Nc] ----------------
template <bool EPI>
__global__ __launch_bounds__(256) void k_gemm(
    const float* __restrict__ A, const float* __restrict__ W, float* __restrict__ C,
    int M, int K, int Nc, const float* __restrict__ bias,
    float* __restrict__ bnsum, float* __restrict__ bnsq)
{
    __shared__ float As[16][64];
    __shared__ float Bs[16][64];
    int tid = threadIdx.x;
    int tx = tid & 15;
    int ty = tid >> 4;
    int row0 = blockIdx.y * 64;
    int col0 = blockIdx.x * 64;
    float acc[4][4];
#pragma unroll
    for (int i = 0; i < 4; i++)
#pragma unroll
        for (int j = 0; j < 4; j++) acc[i][j] = 0.f;

    for (int k0 = 0; k0 < K; k0 += 16) {
#pragma unroll
        for (int t = 0; t < 4; t++) {
            int idx = tid + 256 * t;
            int m = idx >> 4, k = idx & 15;
            int gm = row0 + m;
            As[k][m] = (gm < M) ? A[(size_t)gm * K + k0 + k] : 0.f;
        }
#pragma unroll
        for (int t = 0; t < 4; t++) {
            int idx = tid + 256 * t;
            int k = idx >> 6, nn = idx & 63;
            int gn = col0 + nn;
            Bs[k][nn] = (gn < Nc) ? W[(size_t)(k0 + k) * Nc + gn] : 0.f;
        }
        __syncthreads();
#pragma unroll
        for (int kk = 0; kk < 16; kk++) {
            float ra[4], rb[4];
#pragma unroll
            for (int i = 0; i < 4; i++) ra[i] = As[kk][ty * 4 + i];
#pragma unroll
            for (int j = 0; j < 4; j++) rb[j] = Bs[kk][tx * 4 + j];
#pragma unroll
            for (int i = 0; i < 4; i++)
#pragma unroll
                for (int j = 0; j < 4; j++) acc[i][j] += ra[i] * rb[j];
        }
        __syncthreads();
    }

    if constexpr (!EPI) {
#pragma unroll
        for (int i = 0; i < 4; i++) {
            int row = row0 + ty * 4 + i;
            if (row >= M) continue;
#pragma unroll
            for (int j = 0; j < 4; j++) {
                int col = col0 + tx * 4 + j;
                if (col < Nc) C[(size_t)row * Nc + col] = acc[i][j];
            }
        }
    } else {
        __shared__ float csum[64];
        __shared__ float csq[64];
        if (tid < 64) { csum[tid] = 0.f; csq[tid] = 0.f; }
        __syncthreads();
#pragma unroll
        for (int i = 0; i < 4; i++) {
            int row = row0 + ty * 4 + i;
#pragma unroll
            for (int j = 0; j < 4; j++) {
                int col = col0 + tx * 4 + j;
                if (row < M && col < Nc) {
                    float v = acc[i][j] + bias[col];
                    C[(size_t)row * Nc + col] = v;
                    atomicAdd(&csum[tx * 4 + j], v);
                    atomicAdd(&csq[tx * 4 + j], v * v);
                }
            }
        }
        __syncthreads();
        if (tid < 64 && col0 + tid < Nc) {
            atomicAdd(&bnsum[col0 + tid], csum[tid]);
            atomicAdd(&bnsq[col0 + tid], csq[tid]);
        }
    }
}

// ---------------- BN finalize + fused affine/relu ----------------
__global__ void k_bn_finalize(const float* __restrict__ g, const float* __restrict__ be,
                              int d, float invN, const float* __restrict__ bnsum,
                              const float* __restrict__ bnsq, float* __restrict__ scale,
                              float* __restrict__ shift) {
    int t = threadIdx.x;
    if (t < d) {
        float mu  = bnsum[t] * invN;
        float var = bnsq[t] * invN - mu * mu;
        float rstd = rsqrtf(fmaxf(var, 0.f) + 1e-5f);
        float sc = g[t] * rstd;
        scale[t] = sc;
        shift[t] = be[t] - mu * sc;
    }
}

__global__ void k_norm_relu(const float* __restrict__ conv, float* __restrict__ xout,
                            const float* __restrict__ scale, const float* __restrict__ shift,
                            int total4, int d) {
    for (int i = blockIdx.x * blockDim.x + threadIdx.x; i < total4; i += gridDim.x * blockDim.x) {
        float4 v = ((const float4*)conv)[i];
        int c = (i * 4) % d;
        float4 sc = *(const float4*)(scale + c);
        float4 sh = *(const float4*)(shift + c);
        v.x = fmaxf(v.x * sc.x + sh.x, 0.f);
        v.y = fmaxf(v.y * sc.y + sh.y, 0.f);
        v.z = fmaxf(v.z * sc.z + sh.z, 0.f);
        v.w = fmaxf(v.w * sc.w + sh.w, 0.f);
        ((float4*)xout)[i] = v;
    }
}

// ---------------- edge head: warp per edge ----------------
__global__ __launch_bounds__(256) void k_edge_out(
    const float* __restrict__ xf, const int* __restrict__ src, const int* __restrict__ dst,
    const float* __restrict__ fcw, const float* __restrict__ fcb,
    float* __restrict__ out, int E)
{
    int warp = (blockIdx.x * blockDim.x + threadIdx.x) >> 5;
    int lane = threadIdx.x & 31;
    if (warp >= E) return;
    int s = src[warp], d = dst[warp];
    float v = __ldg(&xf[(size_t)s * 32 + lane]) * __ldg(&xf[(size_t)d * 32 + lane]) * fcw[lane];
#pragma unroll
    for (int o = 16; o; o >>= 1) v += __shfl_xor_sync(0xffffffffu, v, o);
    if (lane == 0) out[warp] = 1.f / (1.f + expf(-(v + fcb[0])));
}

// ---------------- host ----------------
extern "C" void kernel_launch(void* const* d_in, const int* in_sizes, int n_in,
                              void* d_out, int out_size)
{
    const float* x0 = (const float*)d_in[0];
    const void* ei = d_in[1];
    const float *Wl[5], *bl[5], *gl[5], *bel[5];
    for (int l = 0; l < 5; l++) {
        Wl[l]  = (const float*)d_in[2 + 4 * l];
        bl[l]  = (const float*)d_in[3 + 4 * l];
        gl[l]  = (const float*)d_in[4 + 4 * l];
        bel[l] = (const float*)d_in[5 + 4 * l];
    }
    const float* fcw = (const float*)d_in[22];
    const float* fcb = (const float*)d_in[23];
    float* out = (float*)d_out;

    const int n = NN;
    const int E = NE;
    (void)in_sizes; (void)n_in; (void)out_size;

    float *bufA, *bufB, *bufC, *csrw, *di, *dis, *bn, *scale, *shift;
    int *src, *dst, *cnt, *rowptr, *woff, *csrs, *is64;
    cudaGetSymbolAddress((void**)&bufA,  g_bufA);
    cudaGetSymbolAddress((void**)&bufB,  g_bufB);
    cudaGetSymbolAddress((void**)&bufC,  g_bufC);
    cudaGetSymbolAddress((void**)&src,   g_src);
    cudaGetSymbolAddress((void**)&dst,   g_dst);
    cudaGetSymbolAddress((void**)&cnt,   g_cnt);
    cudaGetSymbolAddress((void**)&rowptr,g_rowptr);
    cudaGetSymbolAddress((void**)&woff,  g_woff);
    cudaGetSymbolAddress((void**)&csrs,  g_csr_src);
    cudaGetSymbolAddress((void**)&csrw,  g_csr_w);
    cudaGetSymbolAddress((void**)&di,    g_di);
    cudaGetSymbolAddress((void**)&dis,   g_dis);
    cudaGetSymbolAddress((void**)&bn,    g_bn);
    cudaGetSymbolAddress((void**)&scale, g_scale);
    cudaGetSymbolAddress((void**)&shift, g_shift);
    cudaGetSymbolAddress((void**)&is64,  g_is64);

    // ---- graph preprocessing (per launch; deterministic up to fp atomic order) ----
    k_detect<<<1, 256>>>((const unsigned int*)ei, is64);
    k_zero_i<<<256, 256>>>(cnt, n);
    k_prep_edges<<<2048, 256>>>(ei, is64, src, dst, cnt, E, n);
    k_deg<<<(n + 255) / 256, 256>>>(cnt, di, dis, n);
    k_scan<<<1, 1024>>>(cnt, rowptr, woff, n);
    k_csr<<<2048, 256>>>(src, dst, dis, woff, csrs, csrw, E);

    // ---- 5 GCN layers; aggregate on the cheaper side of the GEMM ----
    const int dims[6] = {128, 128, 256, 128, 64, 32};
    const bool aggFirst[5] = {true, true, false, false, false};
    const float* xin = x0;
    int aggBlocks = (n + 7) / 8;

    for (int l = 0; l < 5; l++) {
        int K = dims[l], D = dims[l + 1];
        k_zero_f<<<1, 512>>>(bn, 512);
        dim3 gg((D + 63) / 64, (n + 63) / 64);
        if (aggFirst[l]) {
            // s = Agg(x) + di*x  (on K=128 dims), then conv = s@W + b with BN partials
            k_agg<128, false><<<aggBlocks, 256>>>(xin, bufB, rowptr, csrs, csrw, di, n,
                                                  nullptr, nullptr, nullptr);
            k_gemm<true><<<gg, 256>>>(bufB, Wl[l], bufC, n, K, D, bl[l], bn, bn + 256);
        } else {
            // h = x@W (on D dims), then conv = Agg(h) + di*h + b with BN partials
            k_gemm<false><<<gg, 256>>>(xin, Wl[l], bufB, n, K, D, nullptr, nullptr, nullptr);
            if (D == 128)
                k_agg<128, true><<<aggBlocks, 256>>>(bufB, bufC, rowptr, csrs, csrw, di, n,
                                                     bl[l], bn, bn + 256);
            else if (D == 64)
                k_agg<64, true><<<aggBlocks, 256>>>(bufB, bufC, rowptr, csrs, csrw, di, n,
                                                    bl[l], bn, bn + 256);
            else
                k_agg<32, true><<<aggBlocks, 256>>>(bufB, bufC, rowptr, csrs, csrw, di, n,
                                                    bl[l], bn, bn + 256);
        }
        k_bn_finalize<<<1, 256>>>(gl[l], bel[l], D, 1.0f / (float)n, bn, bn + 256, scale, shift);
        int total4 = n * D / 4;
        k_norm_relu<<<1024, 256>>>(bufC, bufA, scale, shift, total4, D);
        xin = bufA;
    }

    // ---- edge head: sigmoid((x[src]*x[dst]) . fc_w + fc_b) ----
    int edgeBlocks = (E + 7) / 8;   // 8 warps (edges) per 256-thread block
    k_edge_out<<<edgeBlocks, 256>>>(bufA, src, dst, fcw, fcb, out, E);
}

// round 3
// speedup vs baseline: 1.5171x; 1.5171x over previous
#include <cuda_runtime.h>
#include <math.h>

#define NN 100000
#define NE 3200000
#define MAXD 256

// ---------------- static device scratch (allocation-free contract) ----------------
__device__ float g_bufA[(size_t)NN * MAXD];
__device__ float g_bufB[(size_t)NN * MAXD];
__device__ float g_bufC[(size_t)NN * MAXD];
__device__ int   g_src[NE];
__device__ int   g_dst[NE];
__device__ int   g_cnt[NN];        // invariant: zero at entry of kernel_launch
__device__ int   g_rowptr[NN + 1];
__device__ int   g_woff[NN];
__device__ int2  g_csre[NE];       // packed {src, weight-bits}
__device__ float g_di[NN];
__device__ float g_dis[NN];
__device__ float g_bn[512];        // invariant: zero at entry (finalize re-zeroes)
__device__ float g_scale[256];
__device__ float g_shift[256];

// ---------------- prep: detect dtype inline, convert, count in-degree ----------------
__global__ void k_prep_edges(const void* __restrict__ ei_raw,
                             int* __restrict__ src, int* __restrict__ dst,
                             int* __restrict__ cnt, int E, int n) {
    // detect int64 vs int32: int64 values < 2^31 have zero odd 32-bit words
    const unsigned int* w = (const unsigned int*)ei_raw;
    unsigned int probe = w[2 * (threadIdx.x & 255) + 1];
    int any = __syncthreads_or(probe != 0u);
    const int is64 = (any == 0);
    const long long* ei64 = (const long long*)ei_raw;
    const int* ei32 = (const int*)ei_raw;
    for (int e = blockIdx.x * blockDim.x + threadIdx.x; e < E; e += gridDim.x * blockDim.x) {
        int s, d;
        if (is64) { s = (int)ei64[e]; d = (int)ei64[(size_t)E + e]; }
        else      { s = ei32[e];      d = ei32[(size_t)E + e]; }
        if ((unsigned)s >= (unsigned)n) s = 0;
        if ((unsigned)d >= (unsigned)n) d = 0;
        src[e] = s;
        dst[e] = d;
        atomicAdd(&cnt[d], 1);
    }
}

// ---------------- single-block tiled coalesced scan + deg + cnt re-zero ----------------
__global__ void k_scan_deg(int* __restrict__ cnt, int* __restrict__ rowptr,
                           int* __restrict__ woff, float* __restrict__ di,
                           float* __restrict__ dis, int n) {
    __shared__ int wsum[32];
    __shared__ int s_off;
    int t = threadIdx.x, lane = t & 31, wid = t >> 5;
    if (t == 0) s_off = 0;
    __syncthreads();
    for (int base = 0; base < n; base += 1024) {
        int i = base + t;
        int c = (i < n) ? cnt[i] : 0;
        if (i < n) cnt[i] = 0;             // restore zero invariant
        int x = c;
#pragma unroll
        for (int o = 1; o < 32; o <<= 1) {
            int v = __shfl_up_sync(0xffffffffu, x, o);
            if (lane >= o) x += v;
        }
        if (lane == 31) wsum[wid] = x;
        __syncthreads();
        if (wid == 0) {
            int y = wsum[lane];
#pragma unroll
            for (int o = 1; o < 32; o <<= 1) {
                int v = __shfl_up_sync(0xffffffffu, y, o);
                if (lane >= o) y += v;
            }
            wsum[lane] = y;
        }
        __syncthreads();
        int wbase = (wid == 0) ? 0 : wsum[wid - 1];
        int excl = x + wbase - c;
        int off0 = s_off;
        if (i < n) {
            int r = off0 + excl;
            rowptr[i] = r;
            woff[i]   = r;
            float dg = (float)c + 1.0f;
            di[i]  = 1.0f / dg;
            dis[i] = rsqrtf(dg);
        }
        __syncthreads();
        if (t == 1023) s_off = off0 + wsum[31];
        __syncthreads();
    }
    if (t == 0) rowptr[n] = s_off;
}

// ---------------- CSR scatter with packed (src, weight) ----------------
__global__ void k_csr(const int* __restrict__ src, const int* __restrict__ dst,
                      const float* __restrict__ dis, int* __restrict__ woff,
                      int2* __restrict__ csre, int E) {
    for (int e = blockIdx.x * blockDim.x + threadIdx.x; e < E; e += gridDim.x * blockDim.x) {
        int d = dst[e];
        int pos = atomicAdd(&woff[d], 1);
        int s = src[e];
        if (pos < E) {
            float w = dis[s] * dis[d];
            csre[pos] = make_int2(s, __float_as_int(w));
        }
    }
}

// ---------------- aggregation: warp-per-node gather, fused affine+relu on input ----------------
template <int D, bool EPI, bool AFF>
__global__ __launch_bounds__(256) void k_agg(
    const float* __restrict__ xin, float* __restrict__ xout,
    const int* __restrict__ rowptr, const int2* __restrict__ csre,
    const float* __restrict__ di, int n,
    const float* __restrict__ scale, const float* __restrict__ shift,
    const float* __restrict__ bias, float* __restrict__ bnsum, float* __restrict__ bnsq)
{
    constexpr int CPL = D / 32;
    int lane = threadIdx.x & 31;
    int node = blockIdx.x * 8 + (threadIdx.x >> 5);
    float acc[CPL];
    float sc[CPL], sh[CPL];
#pragma unroll
    for (int j = 0; j < CPL; j++) {
        acc[j] = 0.f;
        if (AFF) { sc[j] = scale[lane + 32 * j]; sh[j] = shift[lane + 32 * j]; }
    }

    if (node < n) {
        int beg = rowptr[node], end = rowptr[node + 1];
        int e = beg;
        for (; e + 2 <= end; e += 2) {
            int2 p0 = __ldg(&csre[e]);
            int2 p1 = __ldg(&csre[e + 1]);
            float w0 = __int_as_float(p0.y);
            float w1 = __int_as_float(p1.y);
            const float* r0 = xin + (size_t)p0.x * D + lane;
            const float* r1 = xin + (size_t)p1.x * D + lane;
            float v0[CPL], v1[CPL];
#pragma unroll
            for (int j = 0; j < CPL; j++) v0[j] = __ldg(r0 + 32 * j);
#pragma unroll
            for (int j = 0; j < CPL; j++) v1[j] = __ldg(r1 + 32 * j);
#pragma unroll
            for (int j = 0; j < CPL; j++) {
                float a0 = AFF ? fmaxf(v0[j] * sc[j] + sh[j], 0.f) : v0[j];
                float a1 = AFF ? fmaxf(v1[j] * sc[j] + sh[j], 0.f) : v1[j];
                acc[j] += w0 * a0;
                acc[j] += w1 * a1;
            }
        }
        if (e < end) {
            int2 p0 = __ldg(&csre[e]);
            float w0 = __int_as_float(p0.y);
            const float* r0 = xin + (size_t)p0.x * D + lane;
#pragma unroll
            for (int j = 0; j < CPL; j++) {
                float v = __ldg(r0 + 32 * j);
                float a = AFF ? fmaxf(v * sc[j] + sh[j], 0.f) : v;
                acc[j] += w0 * a;
            }
        }
        float dii = di[node];
        const float* r = xin + (size_t)node * D + lane;
#pragma unroll
        for (int j = 0; j < CPL; j++) {
            float v = __ldg(r + 32 * j);
            float a = AFF ? fmaxf(v * sc[j] + sh[j], 0.f) : v;
            acc[j] += dii * a;
            if (EPI) acc[j] += bias[lane + 32 * j];
            xout[(size_t)node * D + lane + 32 * j] = acc[j];
        }
    }
    if constexpr (EPI) {
        __shared__ float csum[D];
        __shared__ float csq[D];
        for (int t = threadIdx.x; t < D; t += blockDim.x) { csum[t] = 0.f; csq[t] = 0.f; }
        __syncthreads();
        if (node < n) {
#pragma unroll
            for (int j = 0; j < CPL; j++) {
                atomicAdd(&csum[lane + 32 * j], acc[j]);
                atomicAdd(&csq[lane + 32 * j], acc[j] * acc[j]);
            }
        }
        __syncthreads();
        for (int t = threadIdx.x; t < D; t += blockDim.x) {
            atomicAdd(&bnsum[t], csum[t]);
            atomicAdd(&bnsq[t], csq[t]);
        }
    }
}

// ---------------- GEMM: C[M,Nc] = act(A)[M,K] @ W[K,Nc], 128x64 tile, 8x4 micro ----------------
template <bool EPI, bool AFF>
__global__ __launch_bounds__(256) void k_gemm(
    const float* __restrict__ A, const float* __restrict__ W, float* __restrict__ C,
    int M, int K, int Nc,
    const float* __restrict__ scale, const float* __restrict__ shift,
    const float* __restrict__ bias, float* __restrict__ bnsum, float* __restrict__ bnsq)
{
    __shared__ float As[16][128];
    __shared__ float Bs[16][64];
    int tid = threadIdx.x;
    int tx = tid & 15;          // 16 col groups of 4
    int ty = tid >> 4;          // 16 row groups of 8
    int row0 = blockIdx.y * 128;
    int col0 = blockIdx.x * 64;

    float acc[8][4];
#pragma unroll
    for (int i = 0; i < 8; i++)
#pragma unroll
        for (int j = 0; j < 4; j++) acc[i][j] = 0.f;

    int arow = tid >> 2;        // 0..63 (+64 for t=1)
    int afc  = tid & 3;         // float4 index along K-chunk
    int bkr  = tid >> 4;        // 0..15
    int bfc  = tid & 15;        // 0..15 float4 along 64 cols

    for (int k0 = 0; k0 < K; k0 += 16) {
        // A tile: 128 rows x 16 k, loaded as float4 along K, transposed into As[k][m]
#pragma unroll
        for (int t = 0; t < 2; t++) {
            int m = arow + 64 * t;
            int gm = row0 + m;
            float4 v = make_float4(0.f, 0.f, 0.f, 0.f);
            if (gm < M) v = *(const float4*)(A + (size_t)gm * K + k0 + 4 * afc);
            if (AFF) {
                int kk4 = k0 + 4 * afc;
                float4 s4 = *(const float4*)(scale + kk4);
                float4 h4 = *(const float4*)(shift + kk4);
                v.x = fmaxf(v.x * s4.x + h4.x, 0.f);
                v.y = fmaxf(v.y * s4.y + h4.y, 0.f);
                v.z = fmaxf(v.z * s4.z + h4.z, 0.f);
                v.w = fmaxf(v.w * s4.w + h4.w, 0.f);
            }
            As[4 * afc + 0][m] = v.x;
            As[4 * afc + 1][m] = v.y;
            As[4 * afc + 2][m] = v.z;
            As[4 * afc + 3][m] = v.w;
        }
        // B tile: 16 k x 64 cols
        {
            float4 v = make_float4(0.f, 0.f, 0.f, 0.f);
            int gc = col0 + 4 * bfc;
            if (gc < Nc) v = *(const float4*)(W + (size_t)(k0 + bkr) * Nc + gc);
            *(float4*)&Bs[bkr][4 * bfc] = v;
        }
        __syncthreads();
#pragma unroll
        for (int kk = 0; kk < 16; kk++) {
            float4 a0 = *(const float4*)&As[kk][ty * 8];
            float4 a1 = *(const float4*)&As[kk][ty * 8 + 4];
            float4 b  = *(const float4*)&Bs[kk][tx * 4];
            float ra[8] = {a0.x, a0.y, a0.z, a0.w, a1.x, a1.y, a1.z, a1.w};
            float rb[4] = {b.x, b.y, b.z, b.w};
#pragma unroll
            for (int i = 0; i < 8; i++)
#pragma unroll
                for (int j = 0; j < 4; j++) acc[i][j] += ra[i] * rb[j];
        }
        __syncthreads();
    }

    int colbase = col0 + tx * 4;
    bool colok = colbase < Nc;

    if constexpr (!EPI) {
#pragma unroll
        for (int i = 0; i < 8; i++) {
            int row = row0 + ty * 8 + i;
            if (row < M && colok)
                *(float4*)(C + (size_t)row * Nc + colbase) =
                    make_float4(acc[i][0], acc[i][1], acc[i][2], acc[i][3]);
        }
    } else {
        __shared__ float csum[64];
        __shared__ float csq[64];
        if (tid < 64) { csum[tid] = 0.f; csq[tid] = 0.f; }
        __syncthreads();
        float4 b4 = colok ? *(const float4*)(bias + colbase) : make_float4(0.f, 0.f, 0.f, 0.f);
        float tsum[4] = {0.f, 0.f, 0.f, 0.f};
        float tsq[4]  = {0.f, 0.f, 0.f, 0.f};
#pragma unroll
        for (int i = 0; i < 8; i++) {
            int row = row0 + ty * 8 + i;
            if (row < M && colok) {
                float v0 = acc[i][0] + b4.x;
                float v1 = acc[i][1] + b4.y;
                float v2 = acc[i][2] + b4.z;
                float v3 = acc[i][3] + b4.w;
                *(float4*)(C + (size_t)row * Nc + colbase) = make_float4(v0, v1, v2, v3);
                tsum[0] += v0; tsum[1] += v1; tsum[2] += v2; tsum[3] += v3;
                tsq[0] += v0 * v0; tsq[1] += v1 * v1; tsq[2] += v2 * v2; tsq[3] += v3 * v3;
            }
        }
#pragma unroll
        for (int j = 0; j < 4; j++) {
            atomicAdd(&csum[tx * 4 + j], tsum[j]);
            atomicAdd(&csq[tx * 4 + j], tsq[j]);
        }
        __syncthreads();
        if (tid < 64 && col0 + tid < Nc) {
            atomicAdd(&bnsum[col0 + tid], csum[tid]);
            atomicAdd(&bnsq[col0 + tid], csq[tid]);
        }
    }
}

// ---------------- BN finalize: scale/shift from stats, then re-zero stats ----------------
__global__ void k_bn_finalize(const float* __restrict__ g, const float* __restrict__ be,
                              int d, float invN, float* __restrict__ bn,
                              float* __restrict__ scale, float* __restrict__ shift) {
    int t = threadIdx.x;
    float s = bn[t], q = bn[256 + t];
    if (t < d) {
        float mu  = s * invN;
        float var = q * invN - mu * mu;
        float rstd = rsqrtf(fmaxf(var, 0.f) + 1e-5f);
        float sc = g[t] * rstd;
        scale[t] = sc;
        shift[t] = be[t] - mu * sc;
    }
    bn[t] = 0.f;          // restore zero invariant
    bn[256 + t] = 0.f;
}

// ---------------- edge head: 2 edges per warp, fused affine+relu ----------------
__global__ __launch_bounds__(256) void k_edge_out(
    const float* __restrict__ conv, const int* __restrict__ src, const int* __restrict__ dst,
    const float* __restrict__ scale, const float* __restrict__ shift,
    const float* __restrict__ fcw, const float* __restrict__ fcb,
    float* __restrict__ out, int E)
{
    int warp = (blockIdx.x * blockDim.x + threadIdx.x) >> 5;
    int lane = threadIdx.x & 31;
    int half = lane >> 4;
    int l16  = lane & 15;
    int eid = warp * 2 + half;
    if (eid >= E) return;
    int s = src[eid], d = dst[eid];
    const float* rs = conv + (size_t)s * 32;
    const float* rd = conv + (size_t)d * 32;
    float v = 0.f;
#pragma unroll
    for (int p = 0; p < 2; p++) {
        int f = l16 + 16 * p;
        float sc = scale[f], sh = shift[f];
        float a = fmaxf(__ldg(rs + f) * sc + sh, 0.f);
        float b = fmaxf(__ldg(rd + f) * sc + sh, 0.f);
        v += a * b * fcw[f];
    }
#pragma unroll
    for (int o = 8; o; o >>= 1) v += __shfl_xor_sync(0xffffffffu, v, o);
    if (l16 == 0) out[eid] = 1.f / (1.f + expf(-(v + fcb[0])));
}

// ---------------- host ----------------
extern "C" void kernel_launch(void* const* d_in, const int* in_sizes, int n_in,
                              void* d_out, int out_size)
{
    const float* x0 = (const float*)d_in[0];
    const void* ei = d_in[1];
    const float *Wl[5], *bl[5], *gl[5], *bel[5];
    for (int l = 0; l < 5; l++) {
        Wl[l]  = (const float*)d_in[2 + 4 * l];
        bl[l]  = (const float*)d_in[3 + 4 * l];
        gl[l]  = (const float*)d_in[4 + 4 * l];
        bel[l] = (const float*)d_in[5 + 4 * l];
    }
    const float* fcw = (const float*)d_in[22];
    const float* fcb = (const float*)d_in[23];
    float* out = (float*)d_out;
    const int n = NN, E = NE;
    (void)in_sizes; (void)n_in; (void)out_size;

    float *bufA, *bufB, *bufC, *di, *dis, *bn, *scale, *shift;
    int *src, *dst, *cnt, *rowptr, *woff;
    int2* csre;
    cudaGetSymbolAddress((void**)&bufA,  g_bufA);
    cudaGetSymbolAddress((void**)&bufB,  g_bufB);
    cudaGetSymbolAddress((void**)&bufC,  g_bufC);
    cudaGetSymbolAddress((void**)&src,   g_src);
    cudaGetSymbolAddress((void**)&dst,   g_dst);
    cudaGetSymbolAddress((void**)&cnt,   g_cnt);
    cudaGetSymbolAddress((void**)&rowptr,g_rowptr);
    cudaGetSymbolAddress((void**)&woff,  g_woff);
    cudaGetSymbolAddress((void**)&csre,  g_csre);
    cudaGetSymbolAddress((void**)&di,    g_di);
    cudaGetSymbolAddress((void**)&dis,   g_dis);
    cudaGetSymbolAddress((void**)&bn,    g_bn);
    cudaGetSymbolAddress((void**)&scale, g_scale);
    cudaGetSymbolAddress((void**)&shift, g_shift);

    int aggBlocks = (n + 7) / 8;
    float invN = 1.0f / (float)n;

    // prep (cnt and bn arrive zeroed by invariant)
    k_prep_edges<<<2048, 256>>>(ei, src, dst, cnt, E, n);
    k_scan_deg<<<1, 1024>>>(cnt, rowptr, woff, di, dis, n);
    k_csr<<<2048, 256>>>(src, dst, dis, woff, csre, E);

    // L0 (agg-first): agg(x0) -> B ; gemm B@W0 -> C (conv0, stats) ; finalize scale0
    k_agg<128, false, false><<<aggBlocks, 256>>>(x0, bufB, rowptr, csre, di, n,
                                                 nullptr, nullptr, nullptr, nullptr, nullptr);
    {
        dim3 gg((128 + 63) / 64, (n + 127) / 128);
        k_gemm<true, false><<<gg, 256>>>(bufB, Wl[0], bufC, n, 128, 128,
                                         nullptr, nullptr, bl[0], bn, bn + 256);
    }
    k_bn_finalize<<<1, 256>>>(gl[0], bel[0], 128, invN, bn, scale, shift);

    // L1 (agg-first): agg(act(conv0)) -> B ; gemm B@W1 -> A (conv1, stats) ; finalize
    k_agg<128, false, true><<<aggBlocks, 256>>>(bufC, bufB, rowptr, csre, di, n,
                                                scale, shift, nullptr, nullptr, nullptr);
    {
        dim3 gg((256 + 63) / 64, (n + 127) / 128);
        k_gemm<true, false><<<gg, 256>>>(bufB, Wl[1], bufA, n, 128, 256,
                                         nullptr, nullptr, bl[1], bn, bn + 256);
    }
    k_bn_finalize<<<1, 256>>>(gl[1], bel[1], 256, invN, bn, scale, shift);

    // L2 (gemm-first): gemm act(conv1)@W2 -> B ; agg B -> C (conv2, stats) ; finalize
    {
        dim3 gg((128 + 63) / 64, (n + 127) / 128);
        k_gemm<false, true><<<gg, 256>>>(bufA, Wl[2], bufB, n, 256, 128,
                                         scale, shift, nullptr, nullptr, nullptr);
    }
    k_agg<128, true, false><<<aggBlocks, 256>>>(bufB, bufC, rowptr, csre, di, n,
                                                nullptr, nullptr, bl[2], bn, bn + 256);
    k_bn_finalize<<<1, 256>>>(gl[2], bel[2], 128, invN, bn, scale, shift);

    // L3 (gemm-first): gemm act(conv2)@W3 -> B ; agg B -> A (conv3, stats) ; finalize
    {
        dim3 gg((64 + 63) / 64, (n + 127) / 128);
        k_gemm<false, true><<<gg, 256>>>(bufC, Wl[3], bufB, n, 128, 64,
                                         scale, shift, nullptr, nullptr, nullptr);
    }
    k_agg<64, true, false><<<aggBlocks, 256>>>(bufB, bufA, rowptr, csre, di, n,
                                               nullptr, nullptr, bl[3], bn, bn + 256);
    k_bn_finalize<<<1, 256>>>(gl[3], bel[3], 64, invN, bn, scale, shift);

    // L4 (gemm-first): gemm act(conv3)@W4 -> B ; agg B -> C (conv4, stats) ; finalize
    {
        dim3 gg((32 + 63) / 64, (n + 127) / 128);
        k_gemm<false, true><<<gg, 256>>>(bufA, Wl[4], bufB, n, 64, 32,
                                         scale, shift, nullptr, nullptr, nullptr);
    }
    k_agg<32, true, false><<<aggBlocks, 256>>>(bufB, bufC, rowptr, csre, di, n,
                                               nullptr, nullptr, bl[4], bn, bn + 256);
    k_bn_finalize<<<1, 256>>>(gl[4], bel[4], 32, invN, bn, scale, shift);

    // edge head: sigmoid(dot(act(conv4)[s] * act(conv4)[d], fcw) + fcb)
    int edgeBlocks = (E / 2 + 7) / 8;
    k_edge_out<<<edgeBlocks, 256>>>(bufC, src, dst, scale, shift, fcw, fcb, out, E);
}